// round 16
// baseline (speedup 1.0000x reference)
#include <cuda_runtime.h>

// Problem constants
#define CCH     12            // path channels: 1 time + 3 orig + 8 aug
#define TT      1024
#define NCHTOT  16            // chunks per path
#define WPB     4             // chunk-workers per block
#define NBPP    4             // blocks per path
#define CHLEN   64            // chunk 15 has 63 steps (16*64-1 = 1023)
#define NPATH   64            // B(32) * GROUPS(2)
#define NBATCH  32
#define SIGC    1884          // 12 + 144 + 1728
#define L2OFF   12
#define L3OFF   156
#define TSTRIDE 68            // padded t-stride of transposed dx
#define SIGQ    471           // SIGC / 4 float4s
#define WSTRIDE 1808          // per-worker phase-A smem floats (16B multiple)

// Scratch (no cudaMalloc allowed)
__device__ __align__(16) float g_part4[NPATH * NBPP * SIGC];  // ~1.9 MB (L2-resident)
__device__ __align__(16) float g_sig [NPATH * SIGC];          // ~0.5 MB
__device__ int g_path_cnt[NPATH];                             // zero-init; self-resetting

// ---------------------------------------------------------------------------
// Kernel 1: grid = (NBPP, NPATH) = 256 blocks, block = 576 (18 full warps,
// zero dead lanes), 2 blocks/SM. Worker w (144 thr) scans chunk hb*4+w
// (<=64 steps, FFMA2-packed S3); in-block 4 -> 1 Chen fold -> g_part4.
// Path gate (cnt 4): last quarter-block stages the path's 4 partials (30 KB,
// L2-hot), folds 3x, writes final signature to g_sig.
// ---------------------------------------------------------------------------
extern __shared__ float pool[];   // union: phase A 4*WSTRIDE | fold 4*SIGC

__global__ __launch_bounds__(576, 2) void quarter_path_kernel(
        const float* __restrict__ x,
        const float* __restrict__ aug_w)
{
    __shared__ int sh_last;

    const int tid = threadIdx.x;
    const int hb  = blockIdx.x;          // quarter: chunks hb*4 .. hb*4+3
    const int p   = blockIdx.y;          // path id = b*2 + g
    const int b   = p >> 1;
    const int g   = p & 1;

    const int w   = tid / 144;           // worker 0..3
    const int r   = tid - 144 * w;       // 0..143
    const int chunk = hb * WPB + w;
    const int t0    = chunk * CHLEN;
    const int ns    = (chunk == NCHTOT - 1) ? (CHLEN - 1) : CHLEN;  // 64 or 63

    float* base = pool + w * WSTRIDE;
    float* dxsh = base;                  // [t][c]  64*12 = 768
    float* dxT  = base + 768;            // [c][t]  12*68 = 816
    float* xsh  = base + 1584;           // 195 (+5 pad)
    float* awsh = base + 1784;           // 24

    // ---- Phase A: stage x + weights, build dx (both layouts) ----
    for (int idx = r; idx < (ns + 1) * 3; idx += 144)
        xsh[idx] = x[(b * TT + t0) * 3 + idx];
    if (r < 24) awsh[r] = aug_w[g * 24 + r];
    __syncthreads();

    for (int idx = r; idx < ns * CCH; idx += 144) {
        int t = idx / CCH, c = idx - t * CCH;
        float xd0 = xsh[(t + 1) * 3 + 0] - xsh[t * 3 + 0];
        float xd1 = xsh[(t + 1) * 3 + 1] - xsh[t * 3 + 1];
        float xd2 = xsh[(t + 1) * 3 + 2] - xsh[t * 3 + 2];
        float v;
        if (c == 0)      v = 1.0f / 1023.0f;
        else if (c == 1) v = xd0;
        else if (c == 2) v = xd1;
        else if (c == 3) v = xd2;
        else {
            int e = c - 4;
            v = fmaf(awsh[e * 3 + 0], xd0,
                fmaf(awsh[e * 3 + 1], xd1,
                     awsh[e * 3 + 2] * xd2));
        }
        dxsh[idx] = v;
        dxT[c * TSTRIDE + t] = v;
    }
    __syncthreads();

    // ---- Phase A: scan, thread (i,j) of worker w ----
    const int i = r / CCH, j = r - CCH * (r / CCH);
    unsigned long long S3p[6];
#pragma unroll
    for (int k = 0; k < 6; k++) S3p[k] = 0ULL;
    float S2 = 0.0f;
    float s1 = 0.0f;
    {
        const unsigned long long* __restrict__ dx64 =
            (const unsigned long long*)dxsh;                 // 6 u64 per row
        const float4* __restrict__ diT = (const float4*)(dxT + i * TSTRIDE);
        const float4* __restrict__ djT = (const float4*)(dxT + j * TSTRIDE);

#define SIG_STEP(tq, di_, dj_) {                                              \
        const unsigned long long* dp = dx64 + (size_t)(tq) * 6;               \
        const ulonglong2 v0 = *(const ulonglong2*)(dp);                       \
        const ulonglong2 v1 = *(const ulonglong2*)(dp + 2);                   \
        const ulonglong2 v2 = *(const ulonglong2*)(dp + 4);                   \
        const float cc = fmaf(fmaf((di_), 1.0f/6.0f, 0.5f * s1), (dj_), S2);  \
        unsigned long long ccp;                                               \
        asm("mov.b64 %0, {%1, %1};" : "=l"(ccp) : "f"(cc));                   \
        asm("fma.rn.f32x2 %0, %1, %2, %0;" : "+l"(S3p[0]) : "l"(ccp), "l"(v0.x)); \
        asm("fma.rn.f32x2 %0, %1, %2, %0;" : "+l"(S3p[1]) : "l"(ccp), "l"(v0.y)); \
        asm("fma.rn.f32x2 %0, %1, %2, %0;" : "+l"(S3p[2]) : "l"(ccp), "l"(v1.x)); \
        asm("fma.rn.f32x2 %0, %1, %2, %0;" : "+l"(S3p[3]) : "l"(ccp), "l"(v1.y)); \
        asm("fma.rn.f32x2 %0, %1, %2, %0;" : "+l"(S3p[4]) : "l"(ccp), "l"(v2.x)); \
        asm("fma.rn.f32x2 %0, %1, %2, %0;" : "+l"(S3p[5]) : "l"(ccp), "l"(v2.y)); \
        S2 = fmaf(fmaf((di_), 0.5f, s1), (dj_), S2);                          \
        s1 += (di_); }

        const int nq = ns >> 2;           // 16 or 15
#pragma unroll 4
        for (int tb = 0; tb < nq; tb++) {
            const float4 di4 = diT[tb];
            const float4 dj4 = djT[tb];
            SIG_STEP(tb * 4 + 0, di4.x, dj4.x);
            SIG_STEP(tb * 4 + 1, di4.y, dj4.y);
            SIG_STEP(tb * 4 + 2, di4.z, dj4.z);
            SIG_STEP(tb * 4 + 3, di4.w, dj4.w);
        }
        for (int t = nq * 4; t < ns; t++) {   // remainder (0 or 3 steps)
            const float di = dxT[i * TSTRIDE + t];
            const float dj = dxT[j * TSTRIDE + t];
            SIG_STEP(t, di, dj);
        }
#undef SIG_STEP
    }

    // ---- Phase B: partials -> smem, then in-block 4 -> 1 fold ----
    __syncthreads();   // everyone done reading dx buffers
    {
        float* o = pool + w * SIGC;
        if (j == 0) o[i] = s1;
        o[L2OFF + r] = S2;
        ulonglong2* o2 = (ulonglong2*)(o + L3OFF + r * 12);
        o2[0] = make_ulonglong2(S3p[0], S3p[1]);
        o2[1] = make_ulonglong2(S3p[2], S3p[3]);
        o2[2] = make_ulonglong2(S3p[4], S3p[5]);
    }
    __syncthreads();

    if (tid < 432) {
        const int t144 = tid / 3;
        const int kg   = tid - 3 * t144;
        const int fi   = t144 / CCH;
        const int fj   = t144 - CCH * fi;

        float4 A3   = *(const float4*)(pool + L3OFF + t144 * 12 + kg * 4);
        float  A2ij = pool[L2OFF + t144];
        float  a1i  = pool[fi];

#pragma unroll
        for (int s = 1; s < WPB; s++) {
            const float* __restrict__ bp = pool + s * SIGC;
            const float4 u4  = *(const float4*)(bp + kg * 4);
            const float  b1i = bp[fi];
            const float  b1j = bp[fj];
            const float4 q   = *(const float4*)(bp + L2OFF + fj * 12 + kg * 4);
            const float  b2  = bp[L2OFF + fi * CCH + fj];
            const float4 rr  = *(const float4*)(bp + L3OFF + t144 * 12 + kg * 4);

            A3.x += rr.x; A3.x = fmaf(a1i, q.x, A3.x); A3.x = fmaf(A2ij, u4.x, A3.x);
            A3.y += rr.y; A3.y = fmaf(a1i, q.y, A3.y); A3.y = fmaf(A2ij, u4.y, A3.y);
            A3.z += rr.z; A3.z = fmaf(a1i, q.z, A3.z); A3.z = fmaf(A2ij, u4.z, A3.z);
            A3.w += rr.w; A3.w = fmaf(a1i, q.w, A3.w); A3.w = fmaf(A2ij, u4.w, A3.w);
            A2ij += b2 + a1i * b1j;
            a1i  += b1i;
        }

        float* o = &g_part4[(size_t)(p * NBPP + hb) * SIGC];
        *(float4*)(o + L3OFF + t144 * 12 + kg * 4) = A3;
        if (kg == 0) {
            o[L2OFF + t144] = A2ij;
            if (fj == 0) o[fi] = a1i;
        }
    }

    // --------------- Path gate: last of the 4 quarter-blocks ---------------
    __threadfence();                 // release g_part4 writes
    __syncthreads();
    if (tid == 0) {
        int old = atomicAdd(&g_path_cnt[p], 1);
        sh_last = (old == NBPP - 1);
        if (sh_last) g_path_cnt[p] = 0;      // reset for next replay
    }
    __syncthreads();
    if (!sh_last) return;
    __threadfence();                 // acquire peers' g_part4 writes

    // ---- Gated: stage the 4 quarter-partials, fold 3x, write g_sig ----
    {
        const float4* __restrict__ gsrc =
            (const float4*)&g_part4[(size_t)p * NBPP * SIGC];
        for (int f = tid; f < NBPP * SIGQ; f += 576)
            ((float4*)pool)[f] = gsrc[f];
    }
    __syncthreads();

    if (tid < 432) {
        const int t144 = tid / 3;
        const int kg   = tid - 3 * t144;
        const int fi   = t144 / CCH;
        const int fj   = t144 - CCH * fi;

        float4 A3   = *(const float4*)(pool + L3OFF + t144 * 12 + kg * 4);
        float  A2ij = pool[L2OFF + t144];
        float  a1i  = pool[fi];

#pragma unroll
        for (int s = 1; s < NBPP; s++) {
            const float* __restrict__ bp = pool + (size_t)s * SIGC;
            const float4 u4  = *(const float4*)(bp + kg * 4);
            const float  b1i = bp[fi];
            const float  b1j = bp[fj];
            const float4 q   = *(const float4*)(bp + L2OFF + fj * 12 + kg * 4);
            const float  b2  = bp[L2OFF + fi * CCH + fj];
            const float4 rr  = *(const float4*)(bp + L3OFF + t144 * 12 + kg * 4);

            A3.x += rr.x; A3.x = fmaf(a1i, q.x, A3.x); A3.x = fmaf(A2ij, u4.x, A3.x);
            A3.y += rr.y; A3.y = fmaf(a1i, q.y, A3.y); A3.y = fmaf(A2ij, u4.y, A3.y);
            A3.z += rr.z; A3.z = fmaf(a1i, q.z, A3.z); A3.z = fmaf(A2ij, u4.z, A3.z);
            A3.w += rr.w; A3.w = fmaf(a1i, q.w, A3.w); A3.w = fmaf(A2ij, u4.w, A3.w);
            A2ij += b2 + a1i * b1j;
            a1i  += b1i;
        }

        float* so = &g_sig[(size_t)p * SIGC];
        *(float4*)(so + L3OFF + t144 * 12 + kg * 4) = A3;
        if (kg == 0) {
            so[L2OFF + t144] = A2ij;
            if (fj == 0) so[fi] = a1i;
        }
    }
}

// ---------------------------------------------------------------------------
// Kernel 2: pure GEMV + sigmoid. grid = (NBATCH, 4) = 128 blocks, 1024 thr.
// Block (b, og) computes outputs og*8 .. og*8+7 for batch b.
// Warp w = (o_local = w/4, fq = w%4): dot over ~236 quads of the staged
// sig pair; 4 partials per output summed in smem. Deterministic, gate-free.
// ---------------------------------------------------------------------------
__global__ __launch_bounds__(1024) void gemv_kernel(
        const float* __restrict__ lin_w,
        const float* __restrict__ lin_b,
        float* __restrict__ out)
{
    __shared__ __align__(16) float sig[2 * SIGC];   // 15 KB
    __shared__ float part[8][4];

    const int tid = threadIdx.x;
    const int b   = blockIdx.x;
    const int og  = blockIdx.y;          // output group (8 outputs)

    // Stage the batch's contiguous sig pair
    const float4* __restrict__ gsig =
        (const float4*)&g_sig[(size_t)(2 * b) * SIGC];
    const int NV = (2 * SIGC) / 4;       // 942 quads
    for (int f = tid; f < NV; f += 1024)
        ((float4*)sig)[f] = gsig[f];
    __syncthreads();

    const int wrp  = tid >> 5;           // 0..31
    const int lane = tid & 31;
    const int ol   = wrp >> 2;           // output-local 0..7
    const int fq   = wrp & 3;            // f-quarter 0..3
    const int o    = og * 8 + ol;

    const int fbase = fq * 236;
    const int fend  = (fq == 3) ? NV : fbase + 236;   // 236/236/236/234

    const float4* __restrict__ s4 = (const float4*)sig;
    const float4* __restrict__ w4 = (const float4*)(lin_w + (size_t)o * 2 * SIGC);

    float ax = 0.0f, ay = 0.0f, az = 0.0f, aw = 0.0f;
    for (int f = fbase + lane; f < fend; f += 32) {
        float4 sv = s4[f];
        float4 wv = w4[f];
        ax = fmaf(sv.x, wv.x, ax);
        ay = fmaf(sv.y, wv.y, ay);
        az = fmaf(sv.z, wv.z, az);
        aw = fmaf(sv.w, wv.w, aw);
    }
    float acc = (ax + ay) + (az + aw);
#pragma unroll
    for (int off = 16; off > 0; off >>= 1)
        acc += __shfl_down_sync(0xffffffffu, acc, off);
    if (lane == 0) part[ol][fq] = acc;
    __syncthreads();

    if (tid < 8) {
        float z = (part[tid][0] + part[tid][1])
                + (part[tid][2] + part[tid][3])
                + lin_b[og * 8 + tid];
        out[b * 32 + og * 8 + tid] = 1.0f / (1.0f + expf(-z));
    }
}

// ---------------------------------------------------------------------------
extern "C" void kernel_launch(void* const* d_in, const int* in_sizes, int n_in,
                              void* d_out, int out_size)
{
    const float* x     = (const float*)d_in[0];  // (32,1024,3)
    const float* aug_w = (const float*)d_in[1];  // (2,8,3)
    // d_in[2] = aug_b : unused (signature is translation-invariant)
    const float* lin_w = (const float*)d_in[3];  // (32, 3768)
    const float* lin_b = (const float*)d_in[4];  // (32,)
    float* out = (float*)d_out;                  // (32,32) float32

    // dyn smem: max(phase A 4*WSTRIDE, fold 4*SIGC) floats
    const int dynA = WPB * WSTRIDE;              // 7232
    const int dynB = NBPP * SIGC;                // 7536
    const int dyn_smem = (dynA > dynB ? dynA : dynB) * (int)sizeof(float);  // 30,144 B
    cudaFuncSetAttribute(quarter_path_kernel,
                         cudaFuncAttributeMaxDynamicSharedMemorySize, dyn_smem);

    dim3 grid1(NBPP, NPATH);
    quarter_path_kernel<<<grid1, 576, dyn_smem>>>(x, aug_w);
    dim3 grid2(NBATCH, 4);
    gemv_kernel<<<grid2, 1024>>>(lin_w, lin_b, out);
}

// round 17
// speedup vs baseline: 1.0825x; 1.0825x over previous
#include <cuda_runtime.h>

// Problem constants
#define CCH     12            // path channels: 1 time + 3 orig + 8 aug
#define TT      1024
#define NCHTOT  16            // chunks per path
#define WPB     4             // chunk-workers per block
#define NBPP    4             // blocks per path
#define CHLEN   64            // chunk 15 has 63 steps (16*64-1 = 1023)
#define NPATH   64            // B(32) * GROUPS(2)
#define NBATCH  32
#define SIGC    1884          // 12 + 144 + 1728
#define L2OFF   12
#define L3OFF   156
#define TSTRIDE 68            // padded t-stride of transposed dx
#define SIGQ    471           // SIGC / 4 float4s
#define WSTRIDE 1808          // per-worker phase-A smem floats (16B multiple)

// Scratch (no cudaMalloc allowed)
__device__ __align__(16) float g_part4[NPATH * NBPP * SIGC];  // ~1.9 MB (L2-resident)
__device__ __align__(16) float g_acc[NBATCH * 32 * 2];        // partial dots per (b,o,g)
__device__ int g_cnt[NBATCH];                                 // zero-init; self-resetting

// ---------------------------------------------------------------------------
// Kernel 1: grid = (NBPP, NPATH) = 256 blocks, block = 288 (9 full warps),
// ~3 blocks/SM. Worker w (72 threads) scans chunk hb*4+w; thread (i, jp)
// owns TWO column pairs j=jp and j=jp+6: shared d-quad loads, shared cc
// subexpressions, 12 FFMA2 per step for 24 S3 accumulators.
// Then in-block 4 -> 1 Chen fold (432 items over 288 threads) -> g_part4.
// ---------------------------------------------------------------------------
extern __shared__ float pool[];   // union: phase A 4*WSTRIDE | phase B 4*SIGC

__global__ __launch_bounds__(288, 3) void quarter_path_kernel(
        const float* __restrict__ x,
        const float* __restrict__ aug_w)
{
    const int tid = threadIdx.x;
    const int hb  = blockIdx.x;          // quarter: chunks hb*4 .. hb*4+3
    const int p   = blockIdx.y;          // path id = b*2 + g
    const int b   = p >> 1;
    const int g   = p & 1;

    const int w   = tid / 72;            // worker 0..3
    const int r   = tid - 72 * w;        // 0..71
    const int chunk = hb * WPB + w;
    const int t0    = chunk * CHLEN;
    const int ns    = (chunk == NCHTOT - 1) ? (CHLEN - 1) : CHLEN;  // 64 or 63

    float* base = pool + w * WSTRIDE;
    float* dxsh = base;                  // [t][c]  64*12 = 768
    float* dxT  = base + 768;            // [c][t]  12*68 = 816
    float* xsh  = base + 1584;           // 195 (+5 pad)
    float* awsh = base + 1784;           // 24

    // ---- Phase A: stage x + weights, build dx (both layouts) ----
    for (int idx = r; idx < (ns + 1) * 3; idx += 72)
        xsh[idx] = x[(b * TT + t0) * 3 + idx];
    if (r < 24) awsh[r] = aug_w[g * 24 + r];
    __syncthreads();

    for (int idx = r; idx < ns * CCH; idx += 72) {
        int t = idx / CCH, c = idx - t * CCH;
        float xd0 = xsh[(t + 1) * 3 + 0] - xsh[t * 3 + 0];
        float xd1 = xsh[(t + 1) * 3 + 1] - xsh[t * 3 + 1];
        float xd2 = xsh[(t + 1) * 3 + 2] - xsh[t * 3 + 2];
        float v;
        if (c == 0)      v = 1.0f / 1023.0f;
        else if (c == 1) v = xd0;
        else if (c == 2) v = xd1;
        else if (c == 3) v = xd2;
        else {
            int e = c - 4;
            v = fmaf(awsh[e * 3 + 0], xd0,
                fmaf(awsh[e * 3 + 1], xd1,
                     awsh[e * 3 + 2] * xd2));
        }
        dxsh[idx] = v;
        dxT[c * TSTRIDE + t] = v;
    }
    __syncthreads();

    // ---- Phase A: scan. Thread (i, jp) owns (i, jp) and (i, jp+6). ----
    const int i  = r / 6;                // 0..11
    const int jp = r - 6 * i;            // 0..5
    const int j0 = jp, j1 = jp + 6;

    unsigned long long S3a[6], S3b[6];
#pragma unroll
    for (int k = 0; k < 6; k++) { S3a[k] = 0ULL; S3b[k] = 0ULL; }
    float S2a = 0.0f, S2b = 0.0f;
    float s1 = 0.0f;
    {
        const unsigned long long* __restrict__ dx64 =
            (const unsigned long long*)dxsh;                 // 6 u64 per row
        const float4* __restrict__ diT  = (const float4*)(dxT + i  * TSTRIDE);
        const float4* __restrict__ dj0T = (const float4*)(dxT + j0 * TSTRIDE);
        const float4* __restrict__ dj1T = (const float4*)(dxT + j1 * TSTRIDE);

#define SIG_STEP(tq, di_, dj0_, dj1_) {                                       \
        const unsigned long long* dp = dx64 + (size_t)(tq) * 6;               \
        const ulonglong2 v0 = *(const ulonglong2*)(dp);                       \
        const ulonglong2 v1 = *(const ulonglong2*)(dp + 2);                   \
        const ulonglong2 v2 = *(const ulonglong2*)(dp + 4);                   \
        const float inner = fmaf((di_), 1.0f/6.0f, 0.5f * s1);                \
        const float cc0 = fmaf(inner, (dj0_), S2a);                           \
        const float cc1 = fmaf(inner, (dj1_), S2b);                           \
        unsigned long long cp0, cp1;                                          \
        asm("mov.b64 %0, {%1, %1};" : "=l"(cp0) : "f"(cc0));                  \
        asm("mov.b64 %0, {%1, %1};" : "=l"(cp1) : "f"(cc1));                  \
        asm("fma.rn.f32x2 %0, %1, %2, %0;" : "+l"(S3a[0]) : "l"(cp0), "l"(v0.x)); \
        asm("fma.rn.f32x2 %0, %1, %2, %0;" : "+l"(S3a[1]) : "l"(cp0), "l"(v0.y)); \
        asm("fma.rn.f32x2 %0, %1, %2, %0;" : "+l"(S3a[2]) : "l"(cp0), "l"(v1.x)); \
        asm("fma.rn.f32x2 %0, %1, %2, %0;" : "+l"(S3a[3]) : "l"(cp0), "l"(v1.y)); \
        asm("fma.rn.f32x2 %0, %1, %2, %0;" : "+l"(S3a[4]) : "l"(cp0), "l"(v2.x)); \
        asm("fma.rn.f32x2 %0, %1, %2, %0;" : "+l"(S3a[5]) : "l"(cp0), "l"(v2.y)); \
        asm("fma.rn.f32x2 %0, %1, %2, %0;" : "+l"(S3b[0]) : "l"(cp1), "l"(v0.x)); \
        asm("fma.rn.f32x2 %0, %1, %2, %0;" : "+l"(S3b[1]) : "l"(cp1), "l"(v0.y)); \
        asm("fma.rn.f32x2 %0, %1, %2, %0;" : "+l"(S3b[2]) : "l"(cp1), "l"(v1.x)); \
        asm("fma.rn.f32x2 %0, %1, %2, %0;" : "+l"(S3b[3]) : "l"(cp1), "l"(v1.y)); \
        asm("fma.rn.f32x2 %0, %1, %2, %0;" : "+l"(S3b[4]) : "l"(cp1), "l"(v2.x)); \
        asm("fma.rn.f32x2 %0, %1, %2, %0;" : "+l"(S3b[5]) : "l"(cp1), "l"(v2.y)); \
        const float base2 = fmaf((di_), 0.5f, s1);                            \
        S2a = fmaf(base2, (dj0_), S2a);                                       \
        S2b = fmaf(base2, (dj1_), S2b);                                       \
        s1 += (di_); }

        const int nq = ns >> 2;           // 16 or 15
#pragma unroll 4
        for (int tb = 0; tb < nq; tb++) {
            const float4 di4  = diT[tb];
            const float4 dj04 = dj0T[tb];
            const float4 dj14 = dj1T[tb];
            SIG_STEP(tb * 4 + 0, di4.x, dj04.x, dj14.x);
            SIG_STEP(tb * 4 + 1, di4.y, dj04.y, dj14.y);
            SIG_STEP(tb * 4 + 2, di4.z, dj04.z, dj14.z);
            SIG_STEP(tb * 4 + 3, di4.w, dj04.w, dj14.w);
        }
        for (int t = nq * 4; t < ns; t++) {   // remainder (0 or 3 steps)
            const float di_  = dxT[i  * TSTRIDE + t];
            const float dj0_ = dxT[j0 * TSTRIDE + t];
            const float dj1_ = dxT[j1 * TSTRIDE + t];
            SIG_STEP(t, di_, dj0_, dj1_);
        }
#undef SIG_STEP
    }

    // ---- Phase B: partials -> smem, then in-block 4 -> 1 fold ----
    __syncthreads();   // everyone done reading dx buffers
    {
        float* o = pool + w * SIGC;
        if (jp == 0) o[i] = s1;
        o[L2OFF + i * CCH + j0] = S2a;
        o[L2OFF + i * CCH + j1] = S2b;
        ulonglong2* oa = (ulonglong2*)(o + L3OFF + (i * CCH + j0) * 12);
        oa[0] = make_ulonglong2(S3a[0], S3a[1]);
        oa[1] = make_ulonglong2(S3a[2], S3a[3]);
        oa[2] = make_ulonglong2(S3a[4], S3a[5]);
        ulonglong2* ob = (ulonglong2*)(o + L3OFF + (i * CCH + j1) * 12);
        ob[0] = make_ulonglong2(S3b[0], S3b[1]);
        ob[1] = make_ulonglong2(S3b[2], S3b[3]);
        ob[2] = make_ulonglong2(S3b[4], S3b[5]);
    }
    __syncthreads();

    for (int item = tid; item < 432; item += 288) {
        const int t144 = item / 3;
        const int kg   = item - 3 * t144;
        const int fi   = t144 / CCH;
        const int fj   = t144 - CCH * fi;

        float4 A3   = *(const float4*)(pool + L3OFF + t144 * 12 + kg * 4);
        float  A2ij = pool[L2OFF + t144];
        float  a1i  = pool[fi];

#pragma unroll
        for (int s = 1; s < WPB; s++) {
            const float* __restrict__ bp = pool + s * SIGC;
            const float4 u4  = *(const float4*)(bp + kg * 4);
            const float  b1i = bp[fi];
            const float  b1j = bp[fj];
            const float4 q   = *(const float4*)(bp + L2OFF + fj * 12 + kg * 4);
            const float  b2  = bp[L2OFF + fi * CCH + fj];
            const float4 rr  = *(const float4*)(bp + L3OFF + t144 * 12 + kg * 4);

            A3.x += rr.x; A3.x = fmaf(a1i, q.x, A3.x); A3.x = fmaf(A2ij, u4.x, A3.x);
            A3.y += rr.y; A3.y = fmaf(a1i, q.y, A3.y); A3.y = fmaf(A2ij, u4.y, A3.y);
            A3.z += rr.z; A3.z = fmaf(a1i, q.z, A3.z); A3.z = fmaf(A2ij, u4.z, A3.z);
            A3.w += rr.w; A3.w = fmaf(a1i, q.w, A3.w); A3.w = fmaf(A2ij, u4.w, A3.w);
            A2ij += b2 + a1i * b1j;
            a1i  += b1i;
        }

        float* o = &g_part4[(size_t)(p * NBPP + hb) * SIGC];
        *(float4*)(o + L3OFF + t144 * 12 + kg * 4) = A3;
        if (kg == 0) {
            o[L2OFF + t144] = A2ij;
            if (fj == 0) o[fi] = a1i;
        }
    }
}

// ---------------------------------------------------------------------------
// Kernel 2 (R15 winner, verbatim): per-path final fold + partial GEMV; last
// path of batch does sum + bias + sigmoid. grid = NPATH (64), block = 1024.
// ---------------------------------------------------------------------------
__global__ __launch_bounds__(1024) void finish_kernel(
        const float* __restrict__ lin_w,
        const float* __restrict__ lin_b,
        float* __restrict__ out)
{
    __shared__ __align__(16) float sp[NBPP * SIGC];   // 30.1 KB
    __shared__ int sh_last;

    const int tid = threadIdx.x;
    const int p   = blockIdx.x;          // path = b*2 + g
    const int b   = p >> 1;
    const int g   = p & 1;

    const float4* __restrict__ gsrc =
        (const float4*)&g_part4[(size_t)p * NBPP * SIGC];
    for (int f = tid; f < NBPP * SIGQ; f += 1024)
        ((float4*)sp)[f] = gsrc[f];
    __syncthreads();

    if (tid < 432) {
        const int t144 = tid / 3;
        const int kg   = tid - 3 * t144;
        const int fi   = t144 / CCH;
        const int fj   = t144 - CCH * fi;

        float4 A3   = *(const float4*)(sp + L3OFF + t144 * 12 + kg * 4);
        float  A2ij = sp[L2OFF + t144];
        float  a1i  = sp[fi];

#pragma unroll
        for (int s = 1; s < NBPP; s++) {
            const float* __restrict__ bp = sp + (size_t)s * SIGC;
            const float4 u4  = *(const float4*)(bp + kg * 4);
            const float  b1i = bp[fi];
            const float  b1j = bp[fj];
            const float4 q   = *(const float4*)(bp + L2OFF + fj * 12 + kg * 4);
            const float  b2  = bp[L2OFF + fi * CCH + fj];
            const float4 rr  = *(const float4*)(bp + L3OFF + t144 * 12 + kg * 4);

            A3.x += rr.x; A3.x = fmaf(a1i, q.x, A3.x); A3.x = fmaf(A2ij, u4.x, A3.x);
            A3.y += rr.y; A3.y = fmaf(a1i, q.y, A3.y); A3.y = fmaf(A2ij, u4.y, A3.y);
            A3.z += rr.z; A3.z = fmaf(a1i, q.z, A3.z); A3.z = fmaf(A2ij, u4.z, A3.z);
            A3.w += rr.w; A3.w = fmaf(a1i, q.w, A3.w); A3.w = fmaf(A2ij, u4.w, A3.w);
            A2ij += b2 + a1i * b1j;
            a1i  += b1i;
        }

        *(float4*)(sp + L3OFF + t144 * 12 + kg * 4) = A3;
        if (kg == 0) {
            sp[L2OFF + t144] = A2ij;
            if (fj == 0) sp[fi] = a1i;
        }
    }
    __syncthreads();

    {
        const int o    = tid >> 5;
        const int lane = tid & 31;
        const float4* __restrict__ s4 = (const float4*)sp;
        const float4* __restrict__ w4 =
            (const float4*)(lin_w + (size_t)o * 2 * SIGC + (size_t)g * SIGC);

        float ax = 0.0f, ay = 0.0f, az = 0.0f, aw = 0.0f;
        for (int f = lane; f < SIGQ; f += 32) {
            float4 sv = s4[f];
            float4 wv = w4[f];
            ax = fmaf(sv.x, wv.x, ax);
            ay = fmaf(sv.y, wv.y, ay);
            az = fmaf(sv.z, wv.z, az);
            aw = fmaf(sv.w, wv.w, aw);
        }
        float acc = (ax + ay) + (az + aw);
#pragma unroll
        for (int off = 16; off > 0; off >>= 1)
            acc += __shfl_down_sync(0xffffffffu, acc, off);
        if (lane == 0)
            g_acc[(b * 32 + o) * 2 + g] = acc;
    }

    __threadfence();
    __syncthreads();
    if (tid == 0) {
        int old = atomicAdd(&g_cnt[b], 1);
        sh_last = (old == 1);
        if (sh_last) g_cnt[b] = 0;      // reset for next replay
    }
    __syncthreads();
    if (!sh_last) return;
    __threadfence();                    // acquire other path's g_acc writes

    if (tid < 32) {
        float z = g_acc[(b * 32 + tid) * 2 + 0]
                + g_acc[(b * 32 + tid) * 2 + 1]
                + lin_b[tid];
        out[b * 32 + tid] = 1.0f / (1.0f + expf(-z));
    }
}

// ---------------------------------------------------------------------------
extern "C" void kernel_launch(void* const* d_in, const int* in_sizes, int n_in,
                              void* d_out, int out_size)
{
    const float* x     = (const float*)d_in[0];  // (32,1024,3)
    const float* aug_w = (const float*)d_in[1];  // (2,8,3)
    // d_in[2] = aug_b : unused (signature is translation-invariant)
    const float* lin_w = (const float*)d_in[3];  // (32, 3768)
    const float* lin_b = (const float*)d_in[4];  // (32,)
    float* out = (float*)d_out;                  // (32,32) float32

    // dyn smem: max(phase A 4*WSTRIDE, phase B 4*SIGC) floats
    const int dynA = WPB * WSTRIDE;              // 7232
    const int dynB = NBPP * SIGC;                // 7536
    const int dyn_smem = (dynA > dynB ? dynA : dynB) * (int)sizeof(float);  // 30,144 B
    cudaFuncSetAttribute(quarter_path_kernel,
                         cudaFuncAttributeMaxDynamicSharedMemorySize, dyn_smem);

    dim3 grid1(NBPP, NPATH);
    quarter_path_kernel<<<grid1, 288, dyn_smem>>>(x, aug_w);
    finish_kernel<<<NPATH, 1024>>>(lin_w, lin_b, out);
}